// round 1
// baseline (speedup 1.0000x reference)
#include <cuda_runtime.h>

#define NB  64
#define CCH 3
#define HH  256
#define WW  256
#define DD  512

struct BParam { float m00, m01, m02, m10, m11, m12, w1; int l0; };

__device__ BParam g_bp[NB];
__device__ float g_pyr1[NB * CCH * 128 * 128];
__device__ float g_pyr2[NB * CCH * 64 * 64];
__device__ float g_pyr3[NB * CCH * 32 * 32];

// ---------------------------------------------------------------------------
// Kernel 1: linear head + affine params. One block per batch, 4 warps,
// warp j computes dot(features[n], lin_w[j]).
// ---------------------------------------------------------------------------
__global__ void params_kernel(const float* __restrict__ feat,
                              const float* __restrict__ lw,
                              const float* __restrict__ lb,
                              float* __restrict__ out_mat,
                              float* __restrict__ out_aff) {
    int n = blockIdx.x;
    int warp = threadIdx.x >> 5, lane = threadIdx.x & 31;
    const float* f  = feat + n * DD;
    const float* wr = lw + warp * DD;
    float s = 0.f;
    #pragma unroll 4
    for (int k = lane; k < DD; k += 32) s += f[k] * wr[k];
    #pragma unroll
    for (int o = 16; o; o >>= 1) s += __shfl_xor_sync(0xffffffffu, s, o);
    __shared__ float p[4];
    if (lane == 0) p[warp] = s + lb[warp];
    __syncthreads();
    if (threadIdx.x == 0) {
        float rot = tanhf(p[0]) * 3.14159265358979323846f;
        float sc  = expf(p[1]);
        float sx  = p[2], sy = p[3];
        float cs = cosf(rot), sn = sinf(rot);
        float m00 = sc * cs, m01 = -sc * sn, m10 = sc * sn, m11 = sc * cs;
        float* mo = out_mat + n * 6;
        mo[0] = m00; mo[1] = m01; mo[2] = sx;
        mo[3] = m10; mo[4] = m11; mo[5] = sy;
        float* ao = out_aff + n * 4;
        ao[0] = rot; ao[1] = sc; ao[2] = sx; ao[3] = sy;
        // Affine warp => per-pixel jacobian is constant; with H==W both
        // column norms equal exactly `sc`. levels = clip(log2(max(sc,1)),0,2.5)
        float level = log2f(fmaxf(sc, 1.f));
        level = fminf(fmaxf(level, 0.f), 2.5f);
        int l0 = (int)level;           // level >= 0 so trunc == floor
        if (l0 > 2) l0 = 2;
        BParam bp;
        bp.m00 = m00; bp.m01 = m01; bp.m02 = sx;
        bp.m10 = m10; bp.m11 = m11; bp.m12 = sy;
        bp.w1 = level - (float)l0; bp.l0 = l0;
        g_bp[n] = bp;
    }
}

// ---------------------------------------------------------------------------
// Kernels 2-4: blur+downsample. reflect pad (1,2) then 4x4 stride-2 conv
// with separable [1,3,3,1]/8 kernel. Templated on stage for const sizes.
// ---------------------------------------------------------------------------
template <int STAGE>
__global__ void down_kernel(const float* __restrict__ img) {
    constexpr int Hi = 256 >> STAGE;
    constexpr int Wi = Hi;
    constexpr int Ho = Hi >> 1;
    constexpr int Wo = Wi >> 1;
    constexpr int total = NB * CCH * Ho * Wo;

    const float* in;
    float* out;
    if (STAGE == 0)      { in = img;    out = g_pyr1; }
    else if (STAGE == 1) { in = g_pyr1; out = g_pyr2; }
    else                 { in = g_pyr2; out = g_pyr3; }

    int idx = blockIdx.x * blockDim.x + threadIdx.x;
    if (idx >= total) return;
    int ow = idx & (Wo - 1);
    int t  = idx >> __popc(Wo - 1);      // idx / Wo (Wo is pow2)
    int oh = t & (Ho - 1);
    int nc = t >> __popc(Ho - 1);

    const float* src = in + (size_t)nc * Hi * Wi;
    const float kk[4] = {0.125f, 0.375f, 0.375f, 0.125f};
    int rr[4], cc[4];
    #pragma unroll
    for (int i = 0; i < 4; i++) {
        int r = 2 * oh - 1 + i;
        r = r < 0 ? -r : r;
        r = r >= Hi ? 2 * Hi - 2 - r : r;
        rr[i] = r * Wi;
        int c = 2 * ow - 1 + i;
        c = c < 0 ? -c : c;
        c = c >= Wi ? 2 * Wi - 2 - c : c;
        cc[i] = c;
    }
    float acc = 0.f;
    #pragma unroll
    for (int i = 0; i < 4; i++) {
        float row = kk[0] * __ldg(src + rr[i] + cc[0])
                  + kk[1] * __ldg(src + rr[i] + cc[1])
                  + kk[2] * __ldg(src + rr[i] + cc[2])
                  + kk[3] * __ldg(src + rr[i] + cc[3]);
        acc += kk[i] * row;
    }
    out[idx] = acc;
}

// ---------------------------------------------------------------------------
// Bilinear sample w/ border clamp, accumulate 3 channels scaled by wgt.
// ---------------------------------------------------------------------------
__device__ __forceinline__ void sample_lvl(const float* __restrict__ base, int S,
                                           float gx, float gy, float wgt,
                                           float* acc) {
    float x = (gx + 1.f) * (0.5f * (float)S) - 0.5f;
    float y = (gy + 1.f) * (0.5f * (float)S) - 0.5f;
    float xf = floorf(x), yf = floorf(y);
    float tx = x - xf, ty = y - yf;
    int x0 = (int)xf, y0 = (int)yf;
    int x0c = min(max(x0, 0), S - 1);
    int x1c = min(max(x0 + 1, 0), S - 1);
    int y0c = min(max(y0, 0), S - 1);
    int y1c = min(max(y0 + 1, 0), S - 1);
    float w00 = (1.f - tx) * (1.f - ty) * wgt;
    float w01 = tx * (1.f - ty) * wgt;
    float w10 = (1.f - tx) * ty * wgt;
    float w11 = tx * ty * wgt;
    int r0 = y0c * S, r1 = y1c * S;
    int plane = S * S;
    #pragma unroll
    for (int c = 0; c < 3; c++) {
        const float* p = base + c * plane;
        acc[c] += __ldg(p + r0 + x0c) * w00 + __ldg(p + r0 + x1c) * w01
                + __ldg(p + r1 + x0c) * w10 + __ldg(p + r1 + x1c) * w11;
    }
}

// ---------------------------------------------------------------------------
// Kernel 5: grid gen + mipmap warp. One thread per (n,h,w).
// ---------------------------------------------------------------------------
__global__ void warp_kernel(const float* __restrict__ img,
                            float* __restrict__ out,
                            float2* __restrict__ grid_out) {
    int n = blockIdx.z;
    int w = blockIdx.x * 32 + threadIdx.x;
    int h = blockIdx.y * 8 + threadIdx.y;

    BParam bp = g_bp[n];

    float gxc = ((float)w + 0.5f) * (2.f / (float)WW) - 1.f;
    float gyc = ((float)h + 0.5f) * (2.f / (float)HH) - 1.f;
    float gx = bp.m00 * gxc + bp.m01 * gyc + bp.m02;
    float gy = bp.m10 * gxc + bp.m11 * gyc + bp.m12;

    size_t sp = (size_t)n * HH * WW + (size_t)h * WW + w;
    grid_out[sp] = make_float2(gx, gy);

    float acc[3] = {0.f, 0.f, 0.f};
    int l0 = bp.l0;
    float w1 = bp.w1;
    float w0 = 1.f - w1;

    const float* b0; int s0;
    if (l0 == 0)      { b0 = img    + (size_t)n * CCH * 256 * 256; s0 = 256; }
    else if (l0 == 1) { b0 = g_pyr1 + (size_t)n * CCH * 128 * 128; s0 = 128; }
    else              { b0 = g_pyr2 + (size_t)n * CCH * 64 * 64;   s0 = 64;  }
    sample_lvl(b0, s0, gx, gy, w0, acc);

    if (w1 > 0.f) {
        const float* b1; int s1;
        if (l0 == 0)      { b1 = g_pyr1 + (size_t)n * CCH * 128 * 128; s1 = 128; }
        else if (l0 == 1) { b1 = g_pyr2 + (size_t)n * CCH * 64 * 64;   s1 = 64;  }
        else              { b1 = g_pyr3 + (size_t)n * CCH * 32 * 32;   s1 = 32;  }
        sample_lvl(b1, s1, gx, gy, w1, acc);
    }

    float* o = out + (size_t)n * CCH * HH * WW + (size_t)h * WW + w;
    o[0] = acc[0];
    o[HH * WW] = acc[1];
    o[2 * HH * WW] = acc[2];
}

// ---------------------------------------------------------------------------
extern "C" void kernel_launch(void* const* d_in, const int* in_sizes, int n_in,
                              void* d_out, int out_size) {
    const float* img  = (const float*)d_in[0];
    const float* feat = (const float*)d_in[1];
    const float* lw   = (const float*)d_in[2];
    const float* lb   = (const float*)d_in[3];

    float* base   = (float*)d_out;
    float* out_p  = base;                                   // N*C*H*W
    float* grid_p = base + (size_t)NB * CCH * HH * WW;      // +12582912
    float* mat_p  = grid_p + (size_t)NB * HH * WW * 2;      // +8388608
    float* aff_p  = mat_p + NB * 6;

    params_kernel<<<NB, 128>>>(feat, lw, lb, mat_p, aff_p);

    {
        int total0 = NB * CCH * 128 * 128;
        down_kernel<0><<<(total0 + 255) / 256, 256>>>(img);
        int total1 = NB * CCH * 64 * 64;
        down_kernel<1><<<(total1 + 255) / 256, 256>>>(img);
        int total2 = NB * CCH * 32 * 32;
        down_kernel<2><<<(total2 + 255) / 256, 256>>>(img);
    }

    dim3 blk(32, 8);
    dim3 grd(WW / 32, HH / 8, NB);
    warp_kernel<<<grd, blk>>>(img, out_p, (float2*)grid_p);
}